// round 6
// baseline (speedup 1.0000x reference)
#include <cuda_runtime.h>
#include <cuda_fp16.h>
#include <cstdint>
#include <math.h>

// ---------------- problem constants ----------------
#define T_TOK 8192      // B*S
#define DM    1024
#define DF    4096
#define NE    8
#define GHID  512
#define NSLOT (T_TOK*2)
#define LN_EPS 1e-5f

// ---------------- device scratch ----------------
__device__ float  g_gh[T_TOK * GHID];                 // 16 MB gating hidden
__device__ __half g_xh[(size_t)T_TOK * DM];           // 16 MB fp16 x
__device__ __half g_w1h[(size_t)NE * DF * DM];        // 64 MB, [E][n=F][k=D]
__device__ __half g_w2h[(size_t)NE * DM * DF];        // 64 MB, [E][n=D][k=F]
__device__ __half g_hbuf[(size_t)NSLOT * DF];         // 128 MB fp16 hidden (grouped)
__device__ float  g_eo[(size_t)NSLOT * DM];           // 64 MB per-slot expert out
__device__ int    g_cnt[NE];
__device__ int    g_off[NE];
__device__ int    g_cur[NE];
__device__ int    g_te[T_TOK * 2];
__device__ float  g_tg[T_TOK * 2];
__device__ int    g_slot[T_TOK * 2];
__device__ int    g_tok[NSLOT];
__device__ float  g_psum[NE];
__device__ float  g_loss;

// ---------------- PTX helpers ----------------
__device__ __forceinline__ void mma_f16(float* c, const uint32_t* a, const uint32_t* b) {
    asm volatile(
        "mma.sync.aligned.m16n8k16.row.col.f32.f16.f16.f32 "
        "{%0,%1,%2,%3},{%4,%5,%6,%7},{%8,%9},{%0,%1,%2,%3};"
        : "+f"(c[0]), "+f"(c[1]), "+f"(c[2]), "+f"(c[3])
        : "r"(a[0]), "r"(a[1]), "r"(a[2]), "r"(a[3]), "r"(b[0]), "r"(b[1]));
}
__device__ __forceinline__ void cp16(void* smem, const void* g) {
    uint32_t s = (uint32_t)__cvta_generic_to_shared(smem);
    asm volatile("cp.async.cg.shared.global [%0],[%1],16;" :: "r"(s), "l"(g));
}
__device__ __forceinline__ void cp_commit() { asm volatile("cp.async.commit_group;"); }
__device__ __forceinline__ void cp_wait1() { asm volatile("cp.async.wait_group 1;"); }
__device__ __forceinline__ void cp_wait0() { asm volatile("cp.async.wait_group 0;"); }

// expert GEMM smem geometry: 3 stages, rows of 32 halves (no pad; 2-way LDS conflicts OK)
#define HPITCH 32
#define BKH    32
#define STG_H  (128 * HPITCH)          // halves per matrix per stage = 4096
#define STAGE_H (2 * STG_H)            // A+B per stage = 8192 halves
// 3 * 8192 * 2B = 49152 B = exactly the 48KB static smem limit

// =======================================================================
// Fat prep kernel: gate1 (fp32 SIMT GEMM) + we1/we2 transpose->fp16 + x->fp16 + init.
// Blocks: [0,256) gate1 | [256,8448) trcvt we1 | [8448,16640) trcvt we2 | [16640,20736) cvt_x
// =======================================================================
#define G1_BLOCKS  256
#define TR_BLOCKS  8192
#define CV_BLOCKS  4096
#define PREP_BLOCKS (G1_BLOCKS + 2 * TR_BLOCKS + CV_BLOCKS)

__device__ __forceinline__ void gate1_body(const float* __restrict__ x,
                                           const float* __restrict__ gw1,
                                           const float* __restrict__ gb1,
                                           int bx, int by, float* sm) {
    float* As = sm;          // [8][128]
    float* Bs = sm + 1024;   // [8][128]
    int tid = threadIdx.x;
    int row0 = bx * 128, col0 = by * 128;
    int trow = (tid / 16) * 8, tcol = (tid % 16) * 8;
    int ar = tid >> 1, ak = (tid & 1) * 4;
    int bk = tid >> 5, bn = (tid & 31) * 4;
    const float* Ab = x + (size_t)(row0 + ar) * DM + ak;
    const float* Bb = gw1 + (size_t)bk * GHID + col0 + bn;
    float acc[8][8] = {};
    for (int k0 = 0; k0 < DM; k0 += 8) {
        float4 av = *(const float4*)(Ab + k0);
        As[(ak + 0) * 128 + ar] = av.x; As[(ak + 1) * 128 + ar] = av.y;
        As[(ak + 2) * 128 + ar] = av.z; As[(ak + 3) * 128 + ar] = av.w;
        *(float4*)&Bs[bk * 128 + bn] = *(const float4*)(Bb + (size_t)k0 * GHID);
        __syncthreads();
#pragma unroll
        for (int k = 0; k < 8; k++) {
            float ra[8], rb[8];
#pragma unroll
            for (int i = 0; i < 8; i++) ra[i] = As[k * 128 + trow + i];
#pragma unroll
            for (int j = 0; j < 8; j++) rb[j] = Bs[k * 128 + tcol + j];
#pragma unroll
            for (int i = 0; i < 8; i++)
#pragma unroll
                for (int j = 0; j < 8; j++) acc[i][j] += ra[i] * rb[j];
        }
        __syncthreads();
    }
#pragma unroll
    for (int i = 0; i < 8; i++)
#pragma unroll
        for (int j = 0; j < 8; j++) {
            int r = row0 + trow + i, c = col0 + tcol + j;
            float v = acc[i][j] + gb1[c];
            g_gh[(size_t)r * GHID + c] = fmaxf(v, 0.f);
        }
}

// transpose+convert one 64x64 tile: src[e][R][C] float -> dst[e][C][R] half
__device__ __forceinline__ void trcvt_body(const float* __restrict__ src, __half* __restrict__ dst,
                                           int R, int C, int r_t, int c_t, int e, float* sm) {
    size_t eb = (size_t)e * DM * DF;
    int r0 = r_t * 64, c0 = c_t * 64;
    int tid = threadIdx.x;
    int cl = (tid & 15) * 4, rl = tid >> 4;
#pragma unroll
    for (int i = 0; i < 4; i++) {
        int row = rl + i * 16;
        float4 v = *(const float4*)(src + eb + (size_t)(r0 + row) * C + c0 + cl);
        float* d = sm + row * 66 + cl;
        d[0] = v.x; d[1] = v.y; d[2] = v.z; d[3] = v.w;
    }
    __syncthreads();
    int nl = tid >> 2, kg = (tid & 3) * 16;
    __half hv[16];
#pragma unroll
    for (int j = 0; j < 16; j++) hv[j] = __float2half_rn(sm[(kg + j) * 66 + nl]);
    __half* dp = dst + eb + (size_t)(c0 + nl) * R + r0 + kg;
    *(uint4*)dp = *(uint4*)hv;
    *(uint4*)(dp + 8) = *((uint4*)hv + 1);
}

__global__ __launch_bounds__(256) void k_prep(const float* __restrict__ x,
                                              const float* __restrict__ gw1,
                                              const float* __restrict__ gb1,
                                              const float* __restrict__ we1,
                                              const float* __restrict__ we2) {
    __shared__ __align__(16) float sm[64 * 66];  // 16.9 KB; gate1 uses first 8 KB
    int b = blockIdx.x, tid = threadIdx.x;
    if (b == 0 && tid < NE) { g_cnt[tid] = 0; g_cur[tid] = 0; g_psum[tid] = 0.f; }
    if (b < G1_BLOCKS) { gate1_body(x, gw1, gb1, b % 64, b / 64, sm); return; }
    b -= G1_BLOCKS;
    if (b < TR_BLOCKS) {  // we1 [E][DM][DF] -> g_w1h [E][DF][DM]
        int e = b / 1024, rb = b % 1024;
        trcvt_body(we1, g_w1h, DM, DF, rb / 64, rb % 64, e, sm);
        return;
    }
    b -= TR_BLOCKS;
    if (b < TR_BLOCKS) {  // we2 [E][DF][DM] -> g_w2h [E][DM][DF]
        int e = b / 1024, rb = b % 1024;
        trcvt_body(we2, g_w2h, DF, DM, rb / 16, rb % 16, e, sm);
        return;
    }
    b -= TR_BLOCKS;
    {   // x -> fp16, 8 elements/thread
        size_t i = ((size_t)b * 256 + tid) * 8;
        float4 v0 = *(const float4*)(x + i);
        float4 v1 = *(const float4*)(x + i + 4);
        __half hv[8] = {__float2half_rn(v0.x), __float2half_rn(v0.y),
                        __float2half_rn(v0.z), __float2half_rn(v0.w),
                        __float2half_rn(v1.x), __float2half_rn(v1.y),
                        __float2half_rn(v1.z), __float2half_rn(v1.w)};
        *(uint4*)(g_xh + i) = *(uint4*)hv;
    }
}

// ---------------- gating GEMM2 + top2 + softmax + prob sums ----------------
__global__ void k_gate2(const float* __restrict__ gw2, const float* __restrict__ gb2) {
    __shared__ float s_ps[NE];
    int tid = threadIdx.x, lane = tid & 31, w = tid >> 5;
    if (tid < NE) s_ps[tid] = 0.f;
    __syncthreads();
    int t = blockIdx.x * 8 + w;
    float acc[NE] = {};
    const float* gr = g_gh + (size_t)t * GHID;
    for (int j = lane; j < GHID; j += 32) {
        float v = gr[j];
#pragma unroll
        for (int e = 0; e < NE; e++) acc[e] += v * gw2[j * NE + e];
    }
#pragma unroll
    for (int e = 0; e < NE; e++)
#pragma unroll
        for (int o = 16; o > 0; o >>= 1) acc[e] += __shfl_xor_sync(0xffffffffu, acc[e], o);
    if (lane == 0) {
        float lg[NE];
        float m = -1e30f;
#pragma unroll
        for (int e = 0; e < NE; e++) { lg[e] = acc[e] + gb2[e]; m = fmaxf(m, lg[e]); }
        int i1 = 0, i2 = -1; float v1 = -1e30f, v2 = -1e30f;
#pragma unroll
        for (int e = 0; e < NE; e++) {
            float v = lg[e];
            if (v > v1) { v2 = v1; i2 = i1; v1 = v; i1 = e; }
            else if (v > v2) { v2 = v; i2 = e; }
        }
        float ex = expf(v2 - v1);
        float inv2 = 1.f / (1.f + ex);
        g_te[t * 2 + 0] = i1; g_te[t * 2 + 1] = i2;
        g_tg[t * 2 + 0] = inv2; g_tg[t * 2 + 1] = ex * inv2;
        atomicAdd(&g_cnt[i1], 1);
        atomicAdd(&g_cnt[i2], 1);
        float se = 0.f, pe[NE];
#pragma unroll
        for (int e = 0; e < NE; e++) { pe[e] = expf(lg[e] - m); se += pe[e]; }
        float inv = 1.f / se;
#pragma unroll
        for (int e = 0; e < NE; e++) atomicAdd(&s_ps[e], pe[e] * inv);
    }
    __syncthreads();
    if (tid < NE) atomicAdd(&g_psum[tid], s_ps[tid]);
}

// ---------------- offsets + load loss ----------------
__global__ void k_sched() {
    if (threadIdx.x == 0) {
        int o = 0;
        for (int e = 0; e < NE; e++) { g_off[e] = o; g_cur[e] = o; o += g_cnt[e]; }
        const float tt = 1.f / NE;
        float loss = 0.f;
        for (int e = 0; e < NE; e++) {
            float ep = g_psum[e] / (float)T_TOK;
            loss += tt * (logf(tt) - logf(ep + 1e-8f));
        }
        g_loss = loss;
    }
}

// ---------------- scatter ----------------
__global__ void k_scatter() {
    int t = blockIdx.x * blockDim.x + threadIdx.x;
    if (t >= T_TOK) return;
#pragma unroll
    for (int kk = 0; kk < 2; kk++) {
        int e = g_te[t * 2 + kk];
        int p = atomicAdd(&g_cur[e], 1);
        g_tok[p] = t;
        g_slot[t * 2 + kk] = p;
    }
}

// =======================================================================
// fp16 mma.sync grouped GEMM, 128x128 CTA tile, K-stage 32, 3-stage cp.async.
// MODE 0: hbuf(fp16) = gelu(gather(xh) @ w1h^T + be1)   (K = DM)
// MODE 1: eo(fp32)  = (hbuf @ w2h^T + be2)*escale+ebias (K = DF)
// =======================================================================
template <int MODE>
__global__ __launch_bounds__(256, 2) void k_exp_h(const float* __restrict__ p1,
                                                  const float* __restrict__ p2,
                                                  const float* __restrict__ p3) {
    __shared__ __half sm[3 * STAGE_H];   // 49152 B (exactly 48 KB)
    int e = blockIdx.z;
    int cnt = g_cnt[e];
    int row0 = blockIdx.y * 128;
    if (row0 >= cnt) return;
    int off = g_off[e];
    int col0 = blockIdx.x * 128;
    int tid = threadIdx.x, lane = tid & 31, wid = tid >> 5;
    int m0w = (wid >> 2) * 64;
    int n0w = (wid & 3) * 32;

    const int KD = MODE ? DF : DM;
    // loader: thread covers row r, 2x16B chunks at halves cp0*8, cp0*8+8
    int r = tid >> 1, cp0 = (tid & 1) * 2;
    int arow = row0 + r;
    int arc = arow < cnt ? arow : cnt - 1;
    const __half* arp = MODE ? (g_hbuf + (size_t)(off + arc) * DF)
                             : (g_xh + (size_t)g_tok[off + arc] * DM);
    const __half* brp = (MODE ? g_w2h : g_w1h) + (size_t)e * DM * DF + (size_t)(col0 + r) * KD;
    int ldo = r * HPITCH + cp0 * 8;

    float acc[4][4][4] = {};

    const int NIT = KD / BKH;
    // prologue: stages 0 and 1
#pragma unroll
    for (int s = 0; s < 2; s++) {
        int k0 = s * BKH;
        __half* ad = sm + s * STAGE_H + ldo;
        __half* bd = sm + s * STAGE_H + STG_H + ldo;
        cp16(ad, arp + k0 + cp0 * 8); cp16(ad + 8, arp + k0 + cp0 * 8 + 8);
        cp16(bd, brp + k0 + cp0 * 8); cp16(bd + 8, brp + k0 + cp0 * 8 + 8);
        cp_commit();
    }

    int gr = lane >> 2, c2 = (lane & 3) * 2;
    int st = 0;
    for (int it = 0; it < NIT; it++) {
        if (it < NIT - 2) cp_wait1(); else cp_wait0();
        __syncthreads();
        if (it + 2 < NIT) {
            int k0 = (it + 2) * BKH;
            int ws = st + 2 >= 3 ? st - 1 : st + 2;
            __half* ad = sm + ws * STAGE_H + ldo;
            __half* bd = sm + ws * STAGE_H + STG_H + ldo;
            cp16(ad, arp + k0 + cp0 * 8); cp16(ad + 8, arp + k0 + cp0 * 8 + 8);
            cp16(bd, brp + k0 + cp0 * 8); cp16(bd + 8, brp + k0 + cp0 * 8 + 8);
            cp_commit();
        }
        const __half* Ac = sm + st * STAGE_H;
        const __half* Bc = Ac + STG_H;
#pragma unroll
        for (int q = 0; q < BKH; q += 16) {
            uint32_t af[4][4], bf[4][2];
#pragma unroll
            for (int mi = 0; mi < 4; mi++) {
                const __half* ap = Ac + (m0w + mi * 16 + gr) * HPITCH + q + c2;
                af[mi][0] = *(const uint32_t*)ap;
                af[mi][1] = *(const uint32_t*)(ap + 8 * HPITCH);
                af[mi][2] = *(const uint32_t*)(ap + 8);
                af[mi][3] = *(const uint32_t*)(ap + 8 * HPITCH + 8);
            }
#pragma unroll
            for (int ni = 0; ni < 4; ni++) {
                const __half* bp = Bc + (n0w + ni * 8 + gr) * HPITCH + q + c2;
                bf[ni][0] = *(const uint32_t*)bp;
                bf[ni][1] = *(const uint32_t*)(bp + 8);
            }
#pragma unroll
            for (int mi = 0; mi < 4; mi++)
#pragma unroll
                for (int ni = 0; ni < 4; ni++) mma_f16(acc[mi][ni], af[mi], bf[ni]);
        }
        st = st + 1 == 3 ? 0 : st + 1;
    }

    // epilogue (C frag: rows gr/gr+8, cols c2..c2+1 within each 8-wide ni tile)
#pragma unroll
    for (int mi = 0; mi < 4; mi++) {
#pragma unroll
        for (int half = 0; half < 2; half++) {
            int rr = row0 + m0w + mi * 16 + gr + half * 8;
            if (rr < cnt) {
                if (MODE == 0) {
                    __half* orow = g_hbuf + (size_t)(off + rr) * DF;
                    const float* bb = p1 + e * DF;
#pragma unroll
                    for (int ni = 0; ni < 4; ni++) {
                        int c = col0 + n0w + ni * 8 + c2;
                        float v0 = acc[mi][ni][half * 2 + 0] + bb[c];
                        float v1 = acc[mi][ni][half * 2 + 1] + bb[c + 1];
                        v0 = 0.5f * v0 * (1.f + erff(v0 * 0.70710678118654752f));
                        v1 = 0.5f * v1 * (1.f + erff(v1 * 0.70710678118654752f));
                        *(__half2*)(orow + c) = __floats2half2_rn(v0, v1);
                    }
                } else {
                    float* orow = g_eo + (size_t)(off + rr) * DM;
                    const float* bb = p1 + e * DM;
                    const float* ss = p2 + e * DM;
                    const float* eb = p3 + e * DM;
#pragma unroll
                    for (int ni = 0; ni < 4; ni++) {
                        int c = col0 + n0w + ni * 8 + c2;
                        float v0 = (acc[mi][ni][half * 2 + 0] + bb[c]) * ss[c] + eb[c];
                        float v1 = (acc[mi][ni][half * 2 + 1] + bb[c + 1]) * ss[c + 1] + eb[c + 1];
                        *(float2*)(orow + c) = make_float2(v0, v1);
                    }
                }
            }
        }
    }
}

// ---------------- final: combine top-2 + residual + LayerNorm + loss ----------------
__global__ void k_ln(const float* __restrict__ x, const float* __restrict__ gamma,
                     const float* __restrict__ beta, float* __restrict__ out, int out_size) {
    int t = blockIdx.x;
    int tid = threadIdx.x;
    __shared__ float red[8];
    const float* xr = x + (size_t)t * DM;
    const float* e0 = g_eo + (size_t)g_slot[t * 2 + 0] * DM;
    const float* e1 = g_eo + (size_t)g_slot[t * 2 + 1] * DM;
    float w0 = g_tg[t * 2 + 0], w1 = g_tg[t * 2 + 1];
    float v[4];
    float s = 0.f;
#pragma unroll
    for (int i = 0; i < 4; i++) {
        int c = tid + i * 256;
        v[i] = xr[c] + w0 * e0[c] + w1 * e1[c];
        s += v[i];
    }
#pragma unroll
    for (int o = 16; o > 0; o >>= 1) s += __shfl_xor_sync(0xffffffffu, s, o);
    if ((tid & 31) == 0) red[tid >> 5] = s;
    __syncthreads();
    float tot = 0.f;
#pragma unroll
    for (int i = 0; i < 8; i++) tot += red[i];
    float mu = tot * (1.f / DM);
    float s2 = 0.f;
#pragma unroll
    for (int i = 0; i < 4; i++) { float d = v[i] - mu; s2 += d * d; }
#pragma unroll
    for (int o = 16; o > 0; o >>= 1) s2 += __shfl_xor_sync(0xffffffffu, s2, o);
    __syncthreads();
    if ((tid & 31) == 0) red[tid >> 5] = s2;
    __syncthreads();
    float tot2 = 0.f;
#pragma unroll
    for (int i = 0; i < 8; i++) tot2 += red[i];
    float inv = rsqrtf(tot2 * (1.f / DM) + LN_EPS);
#pragma unroll
    for (int i = 0; i < 4; i++) {
        int c = tid + i * 256;
        out[(size_t)t * DM + c] = (v[i] - mu) * inv * gamma[c] + beta[c];
    }
    if (t == 0 && tid == 0 && out_size > T_TOK * DM) out[T_TOK * DM] = g_loss;
}

// ---------------- launch ----------------
extern "C" void kernel_launch(void* const* d_in, const int* in_sizes, int n_in,
                              void* d_out, int out_size) {
    const float* x      = (const float*)d_in[0];
    const float* gw1    = (const float*)d_in[1];
    const float* gb1    = (const float*)d_in[2];
    const float* gw2    = (const float*)d_in[3];
    const float* gb2    = (const float*)d_in[4];
    const float* we1    = (const float*)d_in[5];
    const float* be1    = (const float*)d_in[6];
    const float* we2    = (const float*)d_in[7];
    const float* be2    = (const float*)d_in[8];
    const float* escale = (const float*)d_in[9];
    const float* ebias  = (const float*)d_in[10];
    const float* gamma  = (const float*)d_in[11];
    const float* beta   = (const float*)d_in[12];
    float* out = (float*)d_out;

    // fused: gate1 GEMM (fp32) + weight transpose/convert + x->fp16 + init
    k_prep<<<PREP_BLOCKS, 256>>>(x, gw1, gb1, we1, we2);

    k_gate2<<<T_TOK / 8, 256>>>(gw2, gb2);
    k_sched<<<1, 32>>>();
    k_scatter<<<(T_TOK + 255) / 256, 256>>>();

    // grouped expert FFN on fp16 mma.sync, 3-stage pipeline (top-2 only)
    k_exp_h<0><<<dim3(DF / 128, 64, NE), 256>>>(be1, nullptr, nullptr);
    k_exp_h<1><<<dim3(DM / 128, 64, NE), 256>>>(be2, escale, ebias);

    // combine + residual + LayerNorm + loss
    k_ln<<<T_TOK, 256>>>(x, gamma, beta, out, out_size);
}

// round 7
// speedup vs baseline: 1.4720x; 1.4720x over previous
#include <cuda_runtime.h>
#include <cuda_fp16.h>
#include <cstdint>
#include <math.h>

// ---------------- problem constants ----------------
#define T_TOK 8192      // B*S
#define DM    1024
#define DF    4096
#define NE    8
#define GHID  512
#define NSLOT (T_TOK*2)
#define LN_EPS 1e-5f

// ---------------- device scratch ----------------
__device__ float  g_gh[T_TOK * GHID];                 // 16 MB gating hidden
__device__ __half g_xh[(size_t)T_TOK * DM];           // 16 MB fp16 x
__device__ __half g_w1h[(size_t)NE * DF * DM];        // 64 MB, [E][n=F][k=D]
__device__ __half g_w2h[(size_t)NE * DM * DF];        // 64 MB, [E][n=D][k=F]
__device__ __half g_hbuf[(size_t)NSLOT * DF];         // 128 MB fp16 hidden (grouped)
__device__ float  g_eo[(size_t)NSLOT * DM];           // 64 MB per-slot expert out
__device__ int    g_cnt[NE];
__device__ int    g_off[NE];
__device__ int    g_cur[NE];
__device__ int    g_te[T_TOK * 2];
__device__ float  g_tg[T_TOK * 2];
__device__ int    g_slot[T_TOK * 2];
__device__ int    g_tok[NSLOT];
__device__ float  g_psum[NE];
__device__ float  g_loss;

// ---------------- PTX helpers ----------------
__device__ __forceinline__ void mma_f16(float* c, const uint32_t* a, const uint32_t* b) {
    asm volatile(
        "mma.sync.aligned.m16n8k16.row.col.f32.f16.f16.f32 "
        "{%0,%1,%2,%3},{%4,%5,%6,%7},{%8,%9},{%0,%1,%2,%3};"
        : "+f"(c[0]), "+f"(c[1]), "+f"(c[2]), "+f"(c[3])
        : "r"(a[0]), "r"(a[1]), "r"(a[2]), "r"(a[3]), "r"(b[0]), "r"(b[1]));
}
__device__ __forceinline__ void cp16(void* smem, const void* g) {
    uint32_t s = (uint32_t)__cvta_generic_to_shared(smem);
    asm volatile("cp.async.cg.shared.global [%0],[%1],16;" :: "r"(s), "l"(g));
}
__device__ __forceinline__ void cp_commit() { asm volatile("cp.async.commit_group;"); }
__device__ __forceinline__ void cp_wait1() { asm volatile("cp.async.wait_group 1;"); }
__device__ __forceinline__ void cp_wait0() { asm volatile("cp.async.wait_group 0;"); }

// smem geometry: rows of 32 data halves padded to 40 (conflict-free fragment loads)
#define HPITCH 40
#define BKH    32
#define STG_H   (128 * HPITCH)        // halves per matrix per stage = 5120
#define STAGE_H (2 * STG_H)           // A+B per stage = 10240 halves = 20480 B
#define NSTAGE  3
#define EXP_SMEM (NSTAGE * STAGE_H * 2)   // 61440 B dynamic

// ---------------- small init ----------------
__global__ void k_init_small() {
    int i = threadIdx.x;
    if (i < NE) { g_cnt[i] = 0; g_cur[i] = 0; g_psum[i] = 0.f; }
}

// ---------------- x -> fp16 ----------------
__global__ void k_cvt_x(const float* __restrict__ x) {
    int i = (blockIdx.x * blockDim.x + threadIdx.x) * 4;
    float4 v = *(const float4*)(x + i);
    __half2* d = (__half2*)(g_xh + i);
    d[0] = __floats2half2_rn(v.x, v.y);
    d[1] = __floats2half2_rn(v.z, v.w);
}

// ---------------- weight transpose+convert: src[e][k][n] -> dst[e][n][k] fp16 ----------------
__global__ void k_trcvt(const float* __restrict__ src, __half* __restrict__ dst,
                        int R /*k*/, int C /*n*/) {
    __shared__ float t[32][33];
    size_t eb = (size_t)blockIdx.z * R * C;
    int c0 = blockIdx.x * 32, r0 = blockIdx.y * 32;
    int tx = threadIdx.x, ty = threadIdx.y;
#pragma unroll
    for (int i = 0; i < 32; i += 8)
        t[ty + i][tx] = src[eb + (size_t)(r0 + ty + i) * C + c0 + tx];
    __syncthreads();
#pragma unroll
    for (int i = 0; i < 32; i += 8)
        dst[eb + (size_t)(c0 + ty + i) * R + r0 + tx] = __float2half_rn(t[tx][ty + i]);
}

// ---------------- gating GEMM1 (fp32 SIMT, routing must stay exact) ----------------
__global__ __launch_bounds__(256) void k_gate1(const float* __restrict__ x,
                                               const float* __restrict__ gw1,
                                               const float* __restrict__ gb1) {
    __shared__ float As[8][128];
    __shared__ float Bs[8][128];
    int tid = threadIdx.x;
    int row0 = blockIdx.x * 128, col0 = blockIdx.y * 128;
    int trow = (tid / 16) * 8, tcol = (tid % 16) * 8;
    int ar = tid >> 1, ak = (tid & 1) * 4;
    int bk = tid >> 5, bn = (tid & 31) * 4;
    const float* Ab = x + (size_t)(row0 + ar) * DM + ak;
    const float* Bb = gw1 + (size_t)bk * GHID + col0 + bn;
    float acc[8][8] = {};
    for (int k0 = 0; k0 < DM; k0 += 8) {
        float4 av = *(const float4*)(Ab + k0);
        As[ak + 0][ar] = av.x; As[ak + 1][ar] = av.y;
        As[ak + 2][ar] = av.z; As[ak + 3][ar] = av.w;
        *(float4*)&Bs[bk][bn] = *(const float4*)(Bb + (size_t)k0 * GHID);
        __syncthreads();
#pragma unroll
        for (int k = 0; k < 8; k++) {
            float ra[8], rb[8];
#pragma unroll
            for (int i = 0; i < 8; i++) ra[i] = As[k][trow + i];
#pragma unroll
            for (int j = 0; j < 8; j++) rb[j] = Bs[k][tcol + j];
#pragma unroll
            for (int i = 0; i < 8; i++)
#pragma unroll
                for (int j = 0; j < 8; j++) acc[i][j] += ra[i] * rb[j];
        }
        __syncthreads();
    }
#pragma unroll
    for (int i = 0; i < 8; i++)
#pragma unroll
        for (int j = 0; j < 8; j++) {
            int r = row0 + trow + i, c = col0 + tcol + j;
            float v = acc[i][j] + gb1[c];
            g_gh[(size_t)r * GHID + c] = fmaxf(v, 0.f);
        }
}

// ---------------- gating GEMM2 + top2 + softmax + prob sums ----------------
__global__ void k_gate2(const float* __restrict__ gw2, const float* __restrict__ gb2) {
    __shared__ float s_ps[NE];
    int tid = threadIdx.x, lane = tid & 31, w = tid >> 5;
    if (tid < NE) s_ps[tid] = 0.f;
    __syncthreads();
    int t = blockIdx.x * 8 + w;
    float acc[NE] = {};
    const float* gr = g_gh + (size_t)t * GHID;
    for (int j = lane; j < GHID; j += 32) {
        float v = gr[j];
#pragma unroll
        for (int e = 0; e < NE; e++) acc[e] += v * gw2[j * NE + e];
    }
#pragma unroll
    for (int e = 0; e < NE; e++)
#pragma unroll
        for (int o = 16; o > 0; o >>= 1) acc[e] += __shfl_xor_sync(0xffffffffu, acc[e], o);
    if (lane == 0) {
        float lg[NE];
        float m = -1e30f;
#pragma unroll
        for (int e = 0; e < NE; e++) { lg[e] = acc[e] + gb2[e]; m = fmaxf(m, lg[e]); }
        int i1 = 0, i2 = -1; float v1 = -1e30f, v2 = -1e30f;
#pragma unroll
        for (int e = 0; e < NE; e++) {
            float v = lg[e];
            if (v > v1) { v2 = v1; i2 = i1; v1 = v; i1 = e; }
            else if (v > v2) { v2 = v; i2 = e; }
        }
        float ex = expf(v2 - v1);
        float inv2 = 1.f / (1.f + ex);
        g_te[t * 2 + 0] = i1; g_te[t * 2 + 1] = i2;
        g_tg[t * 2 + 0] = inv2; g_tg[t * 2 + 1] = ex * inv2;
        atomicAdd(&g_cnt[i1], 1);
        atomicAdd(&g_cnt[i2], 1);
        float se = 0.f, pe[NE];
#pragma unroll
        for (int e = 0; e < NE; e++) { pe[e] = expf(lg[e] - m); se += pe[e]; }
        float inv = 1.f / se;
#pragma unroll
        for (int e = 0; e < NE; e++) atomicAdd(&s_ps[e], pe[e] * inv);
    }
    __syncthreads();
    if (tid < NE) atomicAdd(&g_psum[tid], s_ps[tid]);
}

// ---------------- offsets + load loss ----------------
__global__ void k_sched() {
    if (threadIdx.x == 0) {
        int o = 0;
        for (int e = 0; e < NE; e++) { g_off[e] = o; g_cur[e] = o; o += g_cnt[e]; }
        const float tt = 1.f / NE;
        float loss = 0.f;
        for (int e = 0; e < NE; e++) {
            float ep = g_psum[e] / (float)T_TOK;
            loss += tt * (logf(tt) - logf(ep + 1e-8f));
        }
        g_loss = loss;
    }
}

// ---------------- scatter ----------------
__global__ void k_scatter() {
    int t = blockIdx.x * blockDim.x + threadIdx.x;
    if (t >= T_TOK) return;
#pragma unroll
    for (int kk = 0; kk < 2; kk++) {
        int e = g_te[t * 2 + kk];
        int p = atomicAdd(&g_cur[e], 1);
        g_tok[p] = t;
        g_slot[t * 2 + kk] = p;
    }
}

// =======================================================================
// fp16 mma.sync grouped GEMM, 128x128 CTA tile, K-stage 32, 3-stage cp.async,
// conflict-free smem (pitch 40). Dynamic smem = 61440 B.
// MODE 0: hbuf(fp16) = gelu(gather(xh) @ w1h^T + be1)   (K = DM)
// MODE 1: eo(fp32)  = (hbuf @ w2h^T + be2)*escale+ebias (K = DF)
// =======================================================================
template <int MODE>
__global__ __launch_bounds__(256, 2) void k_exp_h(const float* __restrict__ p1,
                                                  const float* __restrict__ p2,
                                                  const float* __restrict__ p3) {
    extern __shared__ __half sm[];
    int e = blockIdx.z;
    int cnt = g_cnt[e];
    int row0 = blockIdx.y * 128;
    if (row0 >= cnt) return;
    int off = g_off[e];
    int col0 = blockIdx.x * 128;
    int tid = threadIdx.x, lane = tid & 31, wid = tid >> 5;
    int m0w = (wid >> 2) * 64;
    int n0w = (wid & 3) * 32;

    const int KD = MODE ? DF : DM;
    // loader: thread covers row r, 2x16B chunks at halves cp0*8, cp0*8+8
    int r = tid >> 1, cp0 = (tid & 1) * 2;
    int arow = row0 + r;
    int arc = arow < cnt ? arow : cnt - 1;
    const __half* arp = MODE ? (g_hbuf + (size_t)(off + arc) * DF)
                             : (g_xh + (size_t)g_tok[off + arc] * DM);
    const __half* brp = (MODE ? g_w2h : g_w1h) + (size_t)e * DM * DF + (size_t)(col0 + r) * KD;
    int ldo = r * HPITCH + cp0 * 8;

    float acc[4][4][4] = {};

    const int NIT = KD / BKH;
    // prologue: stages 0 and 1
#pragma unroll
    for (int s = 0; s < 2; s++) {
        int k0 = s * BKH;
        __half* ad = sm + s * STAGE_H + ldo;
        __half* bd = sm + s * STAGE_H + STG_H + ldo;
        cp16(ad, arp + k0 + cp0 * 8); cp16(ad + 8, arp + k0 + cp0 * 8 + 8);
        cp16(bd, brp + k0 + cp0 * 8); cp16(bd + 8, brp + k0 + cp0 * 8 + 8);
        cp_commit();
    }

    int gr = lane >> 2, c2 = (lane & 3) * 2;
    int st = 0;
    for (int it = 0; it < NIT; it++) {
        if (it < NIT - 2) cp_wait1(); else cp_wait0();
        __syncthreads();
        if (it + 2 < NIT) {
            int k0 = (it + 2) * BKH;
            int ws = st + 2 >= NSTAGE ? st + 2 - NSTAGE : st + 2;
            __half* ad = sm + ws * STAGE_H + ldo;
            __half* bd = sm + ws * STAGE_H + STG_H + ldo;
            cp16(ad, arp + k0 + cp0 * 8); cp16(ad + 8, arp + k0 + cp0 * 8 + 8);
            cp16(bd, brp + k0 + cp0 * 8); cp16(bd + 8, brp + k0 + cp0 * 8 + 8);
            cp_commit();
        }
        const __half* Ac = sm + st * STAGE_H;
        const __half* Bc = Ac + STG_H;
#pragma unroll
        for (int q = 0; q < BKH; q += 16) {
            uint32_t af[4][4], bf[4][2];
#pragma unroll
            for (int mi = 0; mi < 4; mi++) {
                const __half* ap = Ac + (m0w + mi * 16 + gr) * HPITCH + q + c2;
                af[mi][0] = *(const uint32_t*)ap;
                af[mi][1] = *(const uint32_t*)(ap + 8 * HPITCH);
                af[mi][2] = *(const uint32_t*)(ap + 8);
                af[mi][3] = *(const uint32_t*)(ap + 8 * HPITCH + 8);
            }
#pragma unroll
            for (int ni = 0; ni < 4; ni++) {
                const __half* bp = Bc + (n0w + ni * 8 + gr) * HPITCH + q + c2;
                bf[ni][0] = *(const uint32_t*)bp;
                bf[ni][1] = *(const uint32_t*)(bp + 8);
            }
#pragma unroll
            for (int mi = 0; mi < 4; mi++)
#pragma unroll
                for (int ni = 0; ni < 4; ni++) mma_f16(acc[mi][ni], af[mi], bf[ni]);
        }
        st = st + 1 == NSTAGE ? 0 : st + 1;
    }

    // epilogue (C frag: rows gr/gr+8, cols c2..c2+1 within each 8-wide ni tile)
#pragma unroll
    for (int mi = 0; mi < 4; mi++) {
#pragma unroll
        for (int half = 0; half < 2; half++) {
            int rr = row0 + m0w + mi * 16 + gr + half * 8;
            if (rr < cnt) {
                if (MODE == 0) {
                    __half* orow = g_hbuf + (size_t)(off + rr) * DF;
                    const float* bb = p1 + e * DF;
#pragma unroll
                    for (int ni = 0; ni < 4; ni++) {
                        int c = col0 + n0w + ni * 8 + c2;
                        float v0 = acc[mi][ni][half * 2 + 0] + bb[c];
                        float v1 = acc[mi][ni][half * 2 + 1] + bb[c + 1];
                        v0 = 0.5f * v0 * (1.f + erff(v0 * 0.70710678118654752f));
                        v1 = 0.5f * v1 * (1.f + erff(v1 * 0.70710678118654752f));
                        *(__half2*)(orow + c) = __floats2half2_rn(v0, v1);
                    }
                } else {
                    float* orow = g_eo + (size_t)(off + rr) * DM;
                    const float* bb = p1 + e * DM;
                    const float* ss = p2 + e * DM;
                    const float* eb = p3 + e * DM;
#pragma unroll
                    for (int ni = 0; ni < 4; ni++) {
                        int c = col0 + n0w + ni * 8 + c2;
                        float v0 = (acc[mi][ni][half * 2 + 0] + bb[c]) * ss[c] + eb[c];
                        float v1 = (acc[mi][ni][half * 2 + 1] + bb[c + 1]) * ss[c + 1] + eb[c + 1];
                        *(float2*)(orow + c) = make_float2(v0, v1);
                    }
                }
            }
        }
    }
}

// ---------------- final: combine top-2 + residual + LayerNorm + loss ----------------
__global__ void k_ln(const float* __restrict__ x, const float* __restrict__ gamma,
                     const float* __restrict__ beta, float* __restrict__ out, int out_size) {
    int t = blockIdx.x;
    int tid = threadIdx.x;
    __shared__ float red[8];
    const float* xr = x + (size_t)t * DM;
    const float* e0 = g_eo + (size_t)g_slot[t * 2 + 0] * DM;
    const float* e1 = g_eo + (size_t)g_slot[t * 2 + 1] * DM;
    float w0 = g_tg[t * 2 + 0], w1 = g_tg[t * 2 + 1];
    float v[4];
    float s = 0.f;
#pragma unroll
    for (int i = 0; i < 4; i++) {
        int c = tid + i * 256;
        v[i] = xr[c] + w0 * e0[c] + w1 * e1[c];
        s += v[i];
    }
#pragma unroll
    for (int o = 16; o > 0; o >>= 1) s += __shfl_xor_sync(0xffffffffu, s, o);
    if ((tid & 31) == 0) red[tid >> 5] = s;
    __syncthreads();
    float tot = 0.f;
#pragma unroll
    for (int i = 0; i < 8; i++) tot += red[i];
    float mu = tot * (1.f / DM);
    float s2 = 0.f;
#pragma unroll
    for (int i = 0; i < 4; i++) { float d = v[i] - mu; s2 += d * d; }
#pragma unroll
    for (int o = 16; o > 0; o >>= 1) s2 += __shfl_xor_sync(0xffffffffu, s2, o);
    __syncthreads();
    if ((tid & 31) == 0) red[tid >> 5] = s2;
    __syncthreads();
    float tot2 = 0.f;
#pragma unroll
    for (int i = 0; i < 8; i++) tot2 += red[i];
    float inv = rsqrtf(tot2 * (1.f / DM) + LN_EPS);
#pragma unroll
    for (int i = 0; i < 4; i++) {
        int c = tid + i * 256;
        out[(size_t)t * DM + c] = (v[i] - mu) * inv * gamma[c] + beta[c];
    }
    if (t == 0 && tid == 0 && out_size > T_TOK * DM) out[T_TOK * DM] = g_loss;
}

// ---------------- launch ----------------
extern "C" void kernel_launch(void* const* d_in, const int* in_sizes, int n_in,
                              void* d_out, int out_size) {
    const float* x      = (const float*)d_in[0];
    const float* gw1    = (const float*)d_in[1];
    const float* gb1    = (const float*)d_in[2];
    const float* gw2    = (const float*)d_in[3];
    const float* gb2    = (const float*)d_in[4];
    const float* we1    = (const float*)d_in[5];
    const float* be1    = (const float*)d_in[6];
    const float* we2    = (const float*)d_in[7];
    const float* be2    = (const float*)d_in[8];
    const float* escale = (const float*)d_in[9];
    const float* ebias  = (const float*)d_in[10];
    const float* gamma  = (const float*)d_in[11];
    const float* beta   = (const float*)d_in[12];
    float* out = (float*)d_out;

    cudaFuncSetAttribute(k_exp_h<0>, cudaFuncAttributeMaxDynamicSharedMemorySize, EXP_SMEM);
    cudaFuncSetAttribute(k_exp_h<1>, cudaFuncAttributeMaxDynamicSharedMemorySize, EXP_SMEM);

    k_init_small<<<1, 32>>>();

    // fp16 conversions (x and transposed weights)
    k_cvt_x<<<(T_TOK * DM / 4 + 255) / 256, 256>>>(x);
    {
        __half* w1h; cudaGetSymbolAddress((void**)&w1h, g_w1h);
        __half* w2h; cudaGetSymbolAddress((void**)&w2h, g_w2h);
        k_trcvt<<<dim3(DF / 32, DM / 32, NE), dim3(32, 8)>>>(we1, w1h, DM, DF);
        k_trcvt<<<dim3(DM / 32, DF / 32, NE), dim3(32, 8)>>>(we2, w2h, DF, DM);
    }

    // gating (fp32 — routing decisions must stay exact)
    k_gate1<<<dim3(T_TOK / 128, GHID / 128), 256>>>(x, gw1, gb1);
    k_gate2<<<T_TOK / 8, 256>>>(gw2, gb2);
    k_sched<<<1, 32>>>();
    k_scatter<<<(T_TOK + 255) / 256, 256>>>();

    // grouped expert FFN on fp16 mma.sync, 3-stage pipeline (top-2 only)
    k_exp_h<0><<<dim3(DF / 128, 64, NE), 256, EXP_SMEM>>>(be1, nullptr, nullptr);
    k_exp_h<1><<<dim3(DM / 128, 64, NE), 256, EXP_SMEM>>>(be2, escale, ebias);

    // combine + residual + LayerNorm + loss
    k_ln<<<T_TOK, 256>>>(x, gamma, beta, out, out_size);
}

// round 8
// speedup vs baseline: 1.7004x; 1.1551x over previous
#include <cuda_runtime.h>
#include <cuda_fp16.h>
#include <cstdint>
#include <math.h>

// ---------------- problem constants ----------------
#define T_TOK 8192      // B*S
#define DM    1024
#define DF    4096
#define NE    8
#define GHID  512
#define NSLOT (T_TOK*2)
#define LN_EPS 1e-5f
#define KG1   (3*DM)    // split-gate1 K' = 3072

// ---------------- device scratch ----------------
__device__ float  g_gh[T_TOK * GHID];                 // 16 MB gating hidden (fp32)
__device__ __half g_xh[(size_t)T_TOK * DM];           // 16 MB fp16 x (hi)
__device__ __half g_xlo[(size_t)T_TOK * DM];          // 16 MB fp16 x residual (lo)
__device__ __half g_gw1h[(size_t)GHID * KG1];         // 3 MB  [n=512][k'=3072] = [whi|wlo|whi]
__device__ __half g_w1h[(size_t)NE * DF * DM];        // 64 MB, [E][n=F][k=D]
__device__ __half g_w2h[(size_t)NE * DM * DF];        // 64 MB, [E][n=D][k=F]
__device__ __half g_hbuf[(size_t)NSLOT * DF];         // 128 MB fp16 hidden (grouped)
__device__ float  g_eo[(size_t)NSLOT * DM];           // 64 MB per-slot expert out
__device__ int    g_cnt[NE];
__device__ int    g_off[NE];
__device__ int    g_cur[NE];
__device__ int    g_te[T_TOK * 2];
__device__ float  g_tg[T_TOK * 2];
__device__ int    g_slot[T_TOK * 2];
__device__ int    g_tok[NSLOT];
__device__ float  g_psum[NE];
__device__ float  g_loss;

// ---------------- PTX helpers ----------------
__device__ __forceinline__ void mma_f16(float* c, const uint32_t* a, const uint32_t* b) {
    asm volatile(
        "mma.sync.aligned.m16n8k16.row.col.f32.f16.f16.f32 "
        "{%0,%1,%2,%3},{%4,%5,%6,%7},{%8,%9},{%0,%1,%2,%3};"
        : "+f"(c[0]), "+f"(c[1]), "+f"(c[2]), "+f"(c[3])
        : "r"(a[0]), "r"(a[1]), "r"(a[2]), "r"(a[3]), "r"(b[0]), "r"(b[1]));
}
__device__ __forceinline__ void ldsm4(uint32_t& a, uint32_t& b, uint32_t& c, uint32_t& d,
                                      uint32_t addr) {
    asm volatile("ldmatrix.sync.aligned.m8n8.x4.shared.b16 {%0,%1,%2,%3}, [%4];"
                 : "=r"(a), "=r"(b), "=r"(c), "=r"(d) : "r"(addr));
}
__device__ __forceinline__ void cp16(void* smem, const void* g) {
    uint32_t s = (uint32_t)__cvta_generic_to_shared(smem);
    asm volatile("cp.async.cg.shared.global [%0],[%1],16;" :: "r"(s), "l"(g));
}
__device__ __forceinline__ void cp_commit() { asm volatile("cp.async.commit_group;"); }
__device__ __forceinline__ void cp_wait1() { asm volatile("cp.async.wait_group 1;"); }
__device__ __forceinline__ void cp_wait0() { asm volatile("cp.async.wait_group 0;"); }
__device__ __forceinline__ uint32_t smem_u32(const void* p) {
    uint32_t a;
    asm("{ .reg .u64 t; cvta.to.shared.u64 t, %1; cvt.u32.u64 %0, t; }" : "=r"(a) : "l"(p));
    return a;
}

// smem geometry: rows of 32 data halves padded to 40 (conflict-free)
#define HPITCH 40
#define BKH    32
#define STG_H   (128 * HPITCH)        // halves per matrix per stage = 5120
#define STAGE_H (2 * STG_H)           // A+B per stage
#define NSTAGE  3
#define EXP_SMEM (NSTAGE * STAGE_H * 2)   // 61440 B dynamic

// ---------------- small init ----------------
__global__ void k_init_small() {
    int i = threadIdx.x;
    if (i < NE) { g_cnt[i] = 0; g_cur[i] = 0; g_psum[i] = 0.f; }
}

// ---------------- x -> fp16 hi/lo split ----------------
__global__ void k_cvt_x(const float* __restrict__ x) {
    int i = (blockIdx.x * blockDim.x + threadIdx.x) * 4;
    float4 v = *(const float4*)(x + i);
    __half h[4] = {__float2half_rn(v.x), __float2half_rn(v.y),
                   __float2half_rn(v.z), __float2half_rn(v.w)};
    __half l[4] = {__float2half_rn(v.x - __half2float(h[0])),
                   __float2half_rn(v.y - __half2float(h[1])),
                   __float2half_rn(v.z - __half2float(h[2])),
                   __float2half_rn(v.w - __half2float(h[3]))};
    *(uint2*)(g_xh + i) = *(uint2*)h;
    *(uint2*)(g_xlo + i) = *(uint2*)l;
}

// ---------------- gw1 [k=1024][n=512] -> g_gw1h [n][3072] = [whi|wlo|whi] ----------------
__global__ void k_trg1(const float* __restrict__ gw1) {
    __shared__ float t[32][33];
    int c0 = blockIdx.x * 32, r0 = blockIdx.y * 32;   // c = n, r = k
    int tx = threadIdx.x, ty = threadIdx.y;
#pragma unroll
    for (int i = 0; i < 32; i += 8)
        t[ty + i][tx] = gw1[(size_t)(r0 + ty + i) * GHID + c0 + tx];
    __syncthreads();
#pragma unroll
    for (int i = 0; i < 32; i += 8) {
        int n = c0 + ty + i, k = r0 + tx;
        float v = t[tx][ty + i];
        __half hi = __float2half_rn(v);
        __half lo = __float2half_rn(v - __half2float(hi));
        g_gw1h[(size_t)n * KG1 + k] = hi;
        g_gw1h[(size_t)n * KG1 + DM + k] = lo;
        g_gw1h[(size_t)n * KG1 + 2 * DM + k] = hi;
    }
}

// ---------------- weight transpose+convert: src[e][k][n] -> dst[e][n][k] fp16 ----------------
__global__ void k_trcvt(const float* __restrict__ src, __half* __restrict__ dst,
                        int R /*k*/, int C /*n*/) {
    __shared__ float t[32][33];
    size_t eb = (size_t)blockIdx.z * R * C;
    int c0 = blockIdx.x * 32, r0 = blockIdx.y * 32;
    int tx = threadIdx.x, ty = threadIdx.y;
#pragma unroll
    for (int i = 0; i < 32; i += 8)
        t[ty + i][tx] = src[eb + (size_t)(r0 + ty + i) * C + c0 + tx];
    __syncthreads();
#pragma unroll
    for (int i = 0; i < 32; i += 8)
        dst[eb + (size_t)(c0 + ty + i) * R + r0 + tx] = __float2half_rn(t[tx][ty + i]);
}

// ---------------- gating GEMM2 + top2 + softmax + prob sums ----------------
__global__ void k_gate2(const float* __restrict__ gw2, const float* __restrict__ gb2) {
    __shared__ float s_ps[NE];
    int tid = threadIdx.x, lane = tid & 31, w = tid >> 5;
    if (tid < NE) s_ps[tid] = 0.f;
    __syncthreads();
    int t = blockIdx.x * 8 + w;
    float acc[NE] = {};
    const float* gr = g_gh + (size_t)t * GHID;
    for (int j = lane; j < GHID; j += 32) {
        float v = gr[j];
#pragma unroll
        for (int e = 0; e < NE; e++) acc[e] += v * gw2[j * NE + e];
    }
#pragma unroll
    for (int e = 0; e < NE; e++)
#pragma unroll
        for (int o = 16; o > 0; o >>= 1) acc[e] += __shfl_xor_sync(0xffffffffu, acc[e], o);
    if (lane == 0) {
        float lg[NE];
        float m = -1e30f;
#pragma unroll
        for (int e = 0; e < NE; e++) { lg[e] = acc[e] + gb2[e]; m = fmaxf(m, lg[e]); }
        int i1 = 0, i2 = -1; float v1 = -1e30f, v2 = -1e30f;
#pragma unroll
        for (int e = 0; e < NE; e++) {
            float v = lg[e];
            if (v > v1) { v2 = v1; i2 = i1; v1 = v; i1 = e; }
            else if (v > v2) { v2 = v; i2 = e; }
        }
        float ex = expf(v2 - v1);
        float inv2 = 1.f / (1.f + ex);
        g_te[t * 2 + 0] = i1; g_te[t * 2 + 1] = i2;
        g_tg[t * 2 + 0] = inv2; g_tg[t * 2 + 1] = ex * inv2;
        atomicAdd(&g_cnt[i1], 1);
        atomicAdd(&g_cnt[i2], 1);
        float se = 0.f, pe[NE];
#pragma unroll
        for (int e = 0; e < NE; e++) { pe[e] = expf(lg[e] - m); se += pe[e]; }
        float inv = 1.f / se;
#pragma unroll
        for (int e = 0; e < NE; e++) atomicAdd(&s_ps[e], pe[e] * inv);
    }
    __syncthreads();
    if (tid < NE) atomicAdd(&g_psum[tid], s_ps[tid]);
}

// ---------------- offsets + load loss ----------------
__global__ void k_sched() {
    if (threadIdx.x == 0) {
        int o = 0;
        for (int e = 0; e < NE; e++) { g_off[e] = o; g_cur[e] = o; o += g_cnt[e]; }
        const float tt = 1.f / NE;
        float loss = 0.f;
        for (int e = 0; e < NE; e++) {
            float ep = g_psum[e] / (float)T_TOK;
            loss += tt * (logf(tt) - logf(ep + 1e-8f));
        }
        g_loss = loss;
    }
}

// ---------------- scatter ----------------
__global__ void k_scatter() {
    int t = blockIdx.x * blockDim.x + threadIdx.x;
    if (t >= T_TOK) return;
#pragma unroll
    for (int kk = 0; kk < 2; kk++) {
        int e = g_te[t * 2 + kk];
        int p = atomicAdd(&g_cur[e], 1);
        g_tok[p] = t;
        g_slot[t * 2 + kk] = p;
    }
}

// =======================================================================
// fp16 mma.sync GEMM, 128x128 CTA tile, K-stage 32, 3-stage cp.async,
// ldmatrix fragment loads, conflict-free smem (pitch 40).
// MODE 0: hbuf(fp16) = gelu(gather(xh) @ w1h^T + be1)     (K = DM, grouped)
// MODE 1: eo(fp32)  = (hbuf @ w2h^T + be2)*escale+ebias   (K = DF, grouped)
// MODE 2: gh(fp32)  = relu([xhi|xhi|xlo] @ gw1h^T + gb1)  (K = 3072, dense)
// =======================================================================
template <int MODE>
__global__ __launch_bounds__(256, 2) void k_exp_h(const float* __restrict__ p1,
                                                  const float* __restrict__ p2,
                                                  const float* __restrict__ p3) {
    extern __shared__ __half sm[];
    int e = blockIdx.z;
    int cnt = (MODE == 2) ? T_TOK : g_cnt[e];
    int row0 = blockIdx.y * 128;
    if (row0 >= cnt) return;
    int off = (MODE == 2) ? 0 : g_off[e];
    int col0 = blockIdx.x * 128;
    int tid = threadIdx.x, lane = tid & 31, wid = tid >> 5;
    int m0w = (wid >> 2) * 64;
    int n0w = (wid & 3) * 32;

    const int KD = (MODE == 0) ? DM : (MODE == 1 ? DF : KG1);
    // loader: thread covers row r, halves [cp0h, cp0h+16)
    int r = tid >> 1, cp0h = (tid & 1) * 16;
    int arow = row0 + r;
    int arc = arow < cnt ? arow : cnt - 1;
    const __half* arp_hi;
    const __half* arp_lo = nullptr;
    if (MODE == 0)      arp_hi = g_xh + (size_t)g_tok[off + arc] * DM;
    else if (MODE == 1) arp_hi = g_hbuf + (size_t)(off + arc) * DF;
    else { arp_hi = g_xh + (size_t)arc * DM; arp_lo = g_xlo + (size_t)arc * DM; }
    const __half* brp = (MODE == 2)
        ? (g_gw1h + (size_t)(col0 + r) * KG1)
        : ((MODE ? g_w2h : g_w1h) + (size_t)e * DM * DF + (size_t)(col0 + r) * KD);
    int ldo = r * HPITCH + cp0h;

    // ldmatrix per-lane source offsets (halves)
    int lr = lane & 7;
    int a_radd = ((lane >> 3) & 1) * 8 + lr, a_kadd = (lane >> 4) * 8;
    int b_radd = (lane >> 4) * 8 + lr, b_kadd = ((lane >> 3) & 1) * 8;
    int a_off[4], b_off[2];
#pragma unroll
    for (int mi = 0; mi < 4; mi++) a_off[mi] = (m0w + mi * 16 + a_radd) * HPITCH + a_kadd;
#pragma unroll
    for (int ni = 0; ni < 2; ni++) b_off[ni] = (n0w + ni * 16 + b_radd) * HPITCH + b_kadd;
    uint32_t smu = smem_u32(sm);

    float acc[4][4][4] = {};

    const int NIT = KD / BKH;
    // prologue: stages 0 and 1
#pragma unroll
    for (int s = 0; s < 2; s++) {
        int k0 = s * BKH;
        const __half* as;
        if (MODE == 2) as = (k0 < 2 * DM ? arp_hi + (k0 & (DM - 1)) : arp_lo + (k0 - 2 * DM)) + cp0h;
        else           as = arp_hi + k0 + cp0h;
        __half* ad = sm + s * STAGE_H + ldo;
        __half* bd = sm + s * STAGE_H + STG_H + ldo;
        cp16(ad, as); cp16(ad + 8, as + 8);
        cp16(bd, brp + k0 + cp0h); cp16(bd + 8, brp + k0 + cp0h + 8);
        cp_commit();
    }

    int st = 0;
    for (int it = 0; it < NIT; it++) {
        if (it < NIT - 2) cp_wait1(); else cp_wait0();
        __syncthreads();
        if (it + 2 < NIT) {
            int k0 = (it + 2) * BKH;
            int ws = st + 2 >= NSTAGE ? st + 2 - NSTAGE : st + 2;
            const __half* as;
            if (MODE == 2) as = (k0 < 2 * DM ? arp_hi + (k0 & (DM - 1)) : arp_lo + (k0 - 2 * DM)) + cp0h;
            else           as = arp_hi + k0 + cp0h;
            __half* ad = sm + ws * STAGE_H + ldo;
            __half* bd = sm + ws * STAGE_H + STG_H + ldo;
            cp16(ad, as); cp16(ad + 8, as + 8);
            cp16(bd, brp + k0 + cp0h); cp16(bd + 8, brp + k0 + cp0h + 8);
            cp_commit();
        }
        uint32_t stA = smu + (uint32_t)(st * STAGE_H) * 2;
        uint32_t stB = stA + (uint32_t)STG_H * 2;
#pragma unroll
        for (int q = 0; q < BKH; q += 16) {
            uint32_t af[4][4], bf[4][2];
#pragma unroll
            for (int mi = 0; mi < 4; mi++)
                ldsm4(af[mi][0], af[mi][1], af[mi][2], af[mi][3],
                      stA + (uint32_t)(a_off[mi] + q) * 2);
#pragma unroll
            for (int np = 0; np < 2; np++)
                ldsm4(bf[2 * np][0], bf[2 * np][1], bf[2 * np + 1][0], bf[2 * np + 1][1],
                      stB + (uint32_t)(b_off[np] + q) * 2);
#pragma unroll
            for (int mi = 0; mi < 4; mi++)
#pragma unroll
                for (int ni = 0; ni < 4; ni++) mma_f16(acc[mi][ni], af[mi], bf[ni]);
        }
        st = st + 1 == NSTAGE ? 0 : st + 1;
    }

    // epilogue (C frag: rows gr/gr+8, cols c2..c2+1 in each 8-wide ni tile)
    int gr = lane >> 2, c2 = (lane & 3) * 2;
#pragma unroll
    for (int mi = 0; mi < 4; mi++) {
#pragma unroll
        for (int half = 0; half < 2; half++) {
            int rr = row0 + m0w + mi * 16 + gr + half * 8;
            if (rr < cnt) {
                if (MODE == 0) {
                    __half* orow = g_hbuf + (size_t)(off + rr) * DF;
                    const float* bb = p1 + e * DF;
#pragma unroll
                    for (int ni = 0; ni < 4; ni++) {
                        int c = col0 + n0w + ni * 8 + c2;
                        float v0 = acc[mi][ni][half * 2 + 0] + bb[c];
                        float v1 = acc[mi][ni][half * 2 + 1] + bb[c + 1];
                        v0 = 0.5f * v0 * (1.f + erff(v0 * 0.70710678118654752f));
                        v1 = 0.5f * v1 * (1.f + erff(v1 * 0.70710678118654752f));
                        *(__half2*)(orow + c) = __floats2half2_rn(v0, v1);
                    }
                } else if (MODE == 1) {
                    float* orow = g_eo + (size_t)(off + rr) * DM;
                    const float* bb = p1 + e * DM;
                    const float* ss = p2 + e * DM;
                    const float* eb = p3 + e * DM;
#pragma unroll
                    for (int ni = 0; ni < 4; ni++) {
                        int c = col0 + n0w + ni * 8 + c2;
                        float v0 = (acc[mi][ni][half * 2 + 0] + bb[c]) * ss[c] + eb[c];
                        float v1 = (acc[mi][ni][half * 2 + 1] + bb[c + 1]) * ss[c + 1] + eb[c + 1];
                        *(float2*)(orow + c) = make_float2(v0, v1);
                    }
                } else {
                    float* orow = g_gh + (size_t)rr * GHID;
                    const float* bb = p1;   // gb1
#pragma unroll
                    for (int ni = 0; ni < 4; ni++) {
                        int c = col0 + n0w + ni * 8 + c2;
                        float v0 = fmaxf(acc[mi][ni][half * 2 + 0] + bb[c], 0.f);
                        float v1 = fmaxf(acc[mi][ni][half * 2 + 1] + bb[c + 1], 0.f);
                        *(float2*)(orow + c) = make_float2(v0, v1);
                    }
                }
            }
        }
    }
}

// ---------------- final: combine top-2 + residual + LayerNorm + loss ----------------
__global__ void k_ln(const float* __restrict__ x, const float* __restrict__ gamma,
                     const float* __restrict__ beta, float* __restrict__ out, int out_size) {
    int t = blockIdx.x;
    int tid = threadIdx.x;
    __shared__ float red[8];
    const float* xr = x + (size_t)t * DM;
    const float* e0 = g_eo + (size_t)g_slot[t * 2 + 0] * DM;
    const float* e1 = g_eo + (size_t)g_slot[t * 2 + 1] * DM;
    float w0 = g_tg[t * 2 + 0], w1 = g_tg[t * 2 + 1];
    float v[4];
    float s = 0.f;
#pragma unroll
    for (int i = 0; i < 4; i++) {
        int c = tid + i * 256;
        v[i] = xr[c] + w0 * e0[c] + w1 * e1[c];
        s += v[i];
    }
#pragma unroll
    for (int o = 16; o > 0; o >>= 1) s += __shfl_xor_sync(0xffffffffu, s, o);
    if ((tid & 31) == 0) red[tid >> 5] = s;
    __syncthreads();
    float tot = 0.f;
#pragma unroll
    for (int i = 0; i < 8; i++) tot += red[i];
    float mu = tot * (1.f / DM);
    float s2 = 0.f;
#pragma unroll
    for (int i = 0; i < 4; i++) { float d = v[i] - mu; s2 += d * d; }
#pragma unroll
    for (int o = 16; o > 0; o >>= 1) s2 += __shfl_xor_sync(0xffffffffu, s2, o);
    __syncthreads();
    if ((tid & 31) == 0) red[tid >> 5] = s2;
    __syncthreads();
    float tot2 = 0.f;
#pragma unroll
    for (int i = 0; i < 8; i++) tot2 += red[i];
    float inv = rsqrtf(tot2 * (1.f / DM) + LN_EPS);
#pragma unroll
    for (int i = 0; i < 4; i++) {
        int c = tid + i * 256;
        out[(size_t)t * DM + c] = (v[i] - mu) * inv * gamma[c] + beta[c];
    }
    if (t == 0 && tid == 0 && out_size > T_TOK * DM) out[T_TOK * DM] = g_loss;
}

// ---------------- launch ----------------
extern "C" void kernel_launch(void* const* d_in, const int* in_sizes, int n_in,
                              void* d_out, int out_size) {
    const float* x      = (const float*)d_in[0];
    const float* gw1    = (const float*)d_in[1];
    const float* gb1    = (const float*)d_in[2];
    const float* gw2    = (const float*)d_in[3];
    const float* gb2    = (const float*)d_in[4];
    const float* we1    = (const float*)d_in[5];
    const float* be1    = (const float*)d_in[6];
    const float* we2    = (const float*)d_in[7];
    const float* be2    = (const float*)d_in[8];
    const float* escale = (const float*)d_in[9];
    const float* ebias  = (const float*)d_in[10];
    const float* gamma  = (const float*)d_in[11];
    const float* beta   = (const float*)d_in[12];
    float* out = (float*)d_out;

    cudaFuncSetAttribute(k_exp_h<0>, cudaFuncAttributeMaxDynamicSharedMemorySize, EXP_SMEM);
    cudaFuncSetAttribute(k_exp_h<1>, cudaFuncAttributeMaxDynamicSharedMemorySize, EXP_SMEM);
    cudaFuncSetAttribute(k_exp_h<2>, cudaFuncAttributeMaxDynamicSharedMemorySize, EXP_SMEM);

    k_init_small<<<1, 32>>>();

    // conversions: x hi/lo split, gw1 split-transpose, expert weight transposes
    k_cvt_x<<<(T_TOK * DM / 4 + 255) / 256, 256>>>(x);
    k_trg1<<<dim3(GHID / 32, DM / 32), dim3(32, 8)>>>(gw1);
    {
        __half* w1h; cudaGetSymbolAddress((void**)&w1h, g_w1h);
        __half* w2h; cudaGetSymbolAddress((void**)&w2h, g_w2h);
        k_trcvt<<<dim3(DF / 32, DM / 32, NE), dim3(32, 8)>>>(we1, w1h, DM, DF);
        k_trcvt<<<dim3(DM / 32, DF / 32, NE), dim3(32, 8)>>>(we2, w2h, DF, DM);
    }

    // gating: split-fp16 tensor-core GEMM1 (fp32-accurate), then fp32 gate2
    k_exp_h<2><<<dim3(GHID / 128, T_TOK / 128, 1), 256, EXP_SMEM>>>(gb1, nullptr, nullptr);
    k_gate2<<<T_TOK / 8, 256>>>(gw2, gb2);
    k_sched<<<1, 32>>>();
    k_scatter<<<(T_TOK + 255) / 256, 256>>>();

    // grouped expert FFN on fp16 mma.sync + ldmatrix (top-2 only)
    k_exp_h<0><<<dim3(DF / 128, 64, NE), 256, EXP_SMEM>>>(be1, nullptr, nullptr);
    k_exp_h<1><<<dim3(DM / 128, 64, NE), 256, EXP_SMEM>>>(be2, escale, ebias);

    // combine + residual + LayerNorm + loss
    k_ln<<<T_TOK, 256>>>(x, gamma, beta, out, out_size);
}